// round 1
// baseline (speedup 1.0000x reference)
#include <cuda_runtime.h>

#define BS    2048
#define NINP  512
#define NHID  512
#define KBLK  16
#define TT    8
#define MM    32
#define NTOT  (BS*KBLK)        // 32768
#define GI_COLS (TT*3*MM)      // 768

// scratch for gi = x @ W_ih^T + b_ih, per-b (k-independent)
__device__ float g_gi[BS * GI_COLS];   // [2048][768], 6 MB

// ---------------------------------------------------------------------------
// Kernel 1: gi[b][t*96+g] = sum_k x[b][k]*W_ih[t][g][k] + b_ih[t][g]
// C[2048,768] = A[2048,512] * B[768,512]^T + bias
// ---------------------------------------------------------------------------
__global__ void __launch_bounds__(256) gemm_gi_kernel(
    const float* __restrict__ A,
    const float* __restrict__ B,
    const float* __restrict__ bias)
{
    __shared__ float As[32][65];   // [k][m], padded: conflict-free transpose writes
    __shared__ float Bs[32][65];   // [k][n]

    const int tid = threadIdx.x;
    const int tx  = tid & 15;
    const int ty  = tid >> 4;
    const int m0  = blockIdx.y * 64;
    const int n0  = blockIdx.x * 64;
    const int lr  = tid >> 3;            // 0..31
    const int lk  = (tid & 7) * 4;       // 0,4,...,28

    float acc[4][4];
#pragma unroll
    for (int i = 0; i < 4; i++)
#pragma unroll
        for (int j = 0; j < 4; j++) acc[i][j] = 0.f;

    for (int k0 = 0; k0 < NINP; k0 += 32) {
#pragma unroll
        for (int r = 0; r < 2; r++) {
            float4 va = *(const float4*)&A[(m0 + lr + r * 32) * NINP + k0 + lk];
            As[lk + 0][lr + r * 32] = va.x;
            As[lk + 1][lr + r * 32] = va.y;
            As[lk + 2][lr + r * 32] = va.z;
            As[lk + 3][lr + r * 32] = va.w;
            float4 vb = *(const float4*)&B[(n0 + lr + r * 32) * NINP + k0 + lk];
            Bs[lk + 0][lr + r * 32] = vb.x;
            Bs[lk + 1][lr + r * 32] = vb.y;
            Bs[lk + 2][lr + r * 32] = vb.z;
            Bs[lk + 3][lr + r * 32] = vb.w;
        }
        __syncthreads();
#pragma unroll
        for (int k = 0; k < 32; k++) {
            float a[4], b[4];
#pragma unroll
            for (int i = 0; i < 4; i++) a[i] = As[k][ty + i * 16];
#pragma unroll
            for (int j = 0; j < 4; j++) b[j] = Bs[k][tx + j * 16];
#pragma unroll
            for (int i = 0; i < 4; i++)
#pragma unroll
                for (int j = 0; j < 4; j++)
                    acc[i][j] = fmaf(a[i], b[j], acc[i][j]);
        }
        __syncthreads();
    }

#pragma unroll
    for (int j = 0; j < 4; j++) {
        float bj = bias[n0 + tx + j * 16];
#pragma unroll
        for (int i = 0; i < 4; i++)
            g_gi[(m0 + ty + i * 16) * GI_COLS + n0 + tx + j * 16] = acc[i][j] + bj;
    }
}

// ---------------------------------------------------------------------------
// Kernel 2: fused GRU gates + write-key attention + hard gumbel-softmax select
// Warp handles 4 consecutive n (= b*16+k). Lane = hidden unit m/l (M=32).
// ---------------------------------------------------------------------------
#define WS_STRIDE 97     // [t*32+m][97] rows hold 96 gate weights, pad->conflict free
#define AS_STRIDE 33     // [t*32+m][33] rows hold 32 A-matrix cols
#define SMEM_FLOATS (TT*MM*WS_STRIDE + TT*MM*AS_STRIDE + TT*96)
#define SMEM_BYTES  (SMEM_FLOATS * 4)

__global__ void __launch_bounds__(512, 1) fused_gru_kernel(
    const float* __restrict__ h,
    const float* __restrict__ W_hh,
    const float* __restrict__ b_hh,
    const float* __restrict__ w_read,
    const float* __restrict__ w_write,
    const float* __restrict__ gum,
    float* __restrict__ out)
{
    extern __shared__ float sm[];
    float* Ws  = sm;                            // transposed W_hh: [(t*32+m)*97 + g]
    float* Asm = sm + TT * MM * WS_STRIDE;      // A[t][m][l] : [(t*32+m)*33 + l]
    float* bh  = Asm + TT * MM * AS_STRIDE;     // [8][96]

    const int tid = threadIdx.x;

    // ---- block init: stage weights into smem ----
    for (int i = tid; i < TT * 96 * MM; i += blockDim.x) {   // 24576
        int m = i & 31;
        int g = (i >> 5) % 96;
        int t = i / (96 * MM);
        Ws[(t * 32 + m) * WS_STRIDE + g] = W_hh[i];
    }
    for (int i = tid; i < TT * MM * MM; i += blockDim.x) {   // 8192
        int m = i & 31;
        int l = (i >> 5) & 31;
        int t = i >> 10;
        float acc = 0.f;
#pragma unroll
        for (int f = 0; f < 16; f++)
            acc += w_write[(t * 32 + l) * 16 + f] * w_read[m * 16 + f];
        Asm[(t * 32 + m) * AS_STRIDE + l] = acc;
    }
    for (int i = tid; i < TT * 96; i += blockDim.x) bh[i] = b_hh[i];
    __syncthreads();

    const int lane = tid & 31;
    const int warp = tid >> 5;
    const int n0   = blockIdx.x * 64 + warp * 4;

    float h2v[4];
#pragma unroll
    for (int j = 0; j < 4; j++) h2v[j] = h[(n0 + j) * MM + lane];

    float hx[4][8];
    float rmax[4], rsum[4];
    int   amax[4];
#pragma unroll
    for (int j = 0; j < 4; j++) { rmax[j] = -1e30f; rsum[j] = 0.f; amax[j] = 0; }

#pragma unroll
    for (int t = 0; t < 8; t++) {
        float br = bh[t * 96 + lane];
        float bz = bh[t * 96 + 32 + lane];
        float bn = bh[t * 96 + 64 + lane];
        float ar[4], az[4], an[4], av[4];
#pragma unroll
        for (int j = 0; j < 4; j++) { ar[j] = br; az[j] = bz; an[j] = bn; av[j] = 0.f; }

        const float* wbase = Ws  + (t * 32) * WS_STRIDE;
        const float* abase = Asm + (t * 32) * AS_STRIDE;
#pragma unroll
        for (int m = 0; m < 32; m++) {
            float w0 = wbase[m * WS_STRIDE + lane];
            float w1 = wbase[m * WS_STRIDE + 32 + lane];
            float w2 = wbase[m * WS_STRIDE + 64 + lane];
            float wa = abase[m * AS_STRIDE + lane];
#pragma unroll
            for (int j = 0; j < 4; j++) {
                float hm = __shfl_sync(0xffffffffu, h2v[j], m);
                ar[j] = fmaf(w0, hm, ar[j]);
                az[j] = fmaf(w1, hm, az[j]);
                an[j] = fmaf(w2, hm, an[j]);
                av[j] = fmaf(wa, hm, av[j]);
            }
        }

#pragma unroll
        for (int j = 0; j < 4; j++) {
            int b = (n0 + j) >> 4;
            const float* gp = g_gi + b * GI_COLS + t * 96;
            float gr = gp[lane], gz = gp[32 + lane], gn = gp[64 + lane];
            float r  = __fdividef(1.f, 1.f + __expf(-(gr + ar[j])));
            float z  = __fdividef(1.f, 1.f + __expf(-(gz + az[j])));
            float xn = gn + r * an[j];
            float e2 = __expf(-2.f * xn);
            float nn = __fdividef(1.f - e2, 1.f + e2);       // tanh
            float hn = (1.f - z) * nn + z * h2v[j];
            hx[j][t] = hn;

            // logit[t] = sum_l hnext[l] * v[t][l], butterfly -> all lanes
            float lg = hn * av[j];
            lg += __shfl_xor_sync(0xffffffffu, lg, 16);
            lg += __shfl_xor_sync(0xffffffffu, lg, 8);
            lg += __shfl_xor_sync(0xffffffffu, lg, 4);
            lg += __shfl_xor_sync(0xffffffffu, lg, 2);
            lg += __shfl_xor_sync(0xffffffffu, lg, 1);

            float s = (lg + gum[(n0 + j) * 8 + t]) * 2.0f;   // /TAU, TAU=0.5
            if (s > rmax[j]) {
                rsum[j] = rsum[j] * __expf(rmax[j] - s) + 1.f;
                rmax[j] = s;
                amax[j] = t;
            } else {
                rsum[j] += __expf(s - rmax[j]);
            }
        }
    }

    float* h_out   = out;
    float* att_out = out + BS * NHID;

    float attv[4];
#pragma unroll
    for (int j = 0; j < 4; j++) {
        float p = __fdividef(1.f, rsum[j]);     // softmax value at argmax
        attv[j] = (1.f + p) - p;                // straight-through residual, exact
        float hsel = hx[j][0];
#pragma unroll
        for (int t = 1; t < 8; t++)
            if (amax[j] == t) hsel = hx[j][t];
        h_out[(n0 + j) * MM + lane] = attv[j] * hsel;
    }

    // att_out[n][t]: zero except argmax (exact FP cancellation elsewhere)
    int jj = lane >> 3, ts = lane & 7;
    float a_ = attv[0];
    int   tm_ = amax[0];
#pragma unroll
    for (int j = 1; j < 4; j++)
        if (jj == j) { a_ = attv[j]; tm_ = amax[j]; }
    att_out[(n0 + jj) * 8 + ts] = (ts == tm_) ? a_ : 0.f;
}

// ---------------------------------------------------------------------------
extern "C" void kernel_launch(void* const* d_in, const int* in_sizes, int n_in,
                              void* d_out, int out_size)
{
    const float* x       = (const float*)d_in[0];
    const float* h       = (const float*)d_in[1];
    const float* W_ih    = (const float*)d_in[2];
    const float* W_hh    = (const float*)d_in[3];
    const float* b_ih    = (const float*)d_in[4];
    const float* b_hh    = (const float*)d_in[5];
    const float* w_read  = (const float*)d_in[6];
    const float* w_write = (const float*)d_in[7];
    const float* gum     = (const float*)d_in[8];
    float* out = (float*)d_out;

    dim3 g1(GI_COLS / 64, BS / 64);           // (12, 32)
    gemm_gi_kernel<<<g1, 256>>>(x, W_ih, b_ih);

    cudaFuncSetAttribute(fused_gru_kernel,
                         cudaFuncAttributeMaxDynamicSharedMemorySize, SMEM_BYTES);
    fused_gru_kernel<<<NTOT / 64, 512, SMEM_BYTES>>>(
        h, W_hh, b_hh, w_read, w_write, gum, out);
}

// round 2
// speedup vs baseline: 2.2012x; 2.2012x over previous
#include <cuda_runtime.h>

#define BS    2048
#define NINP  512
#define NHID  512
#define KBLK  16
#define TT    8
#define MM    32
#define NTOT  (BS*KBLK)        // 32768
#define GI_COLS (TT*3*MM)      // 768
#define TPB   224              // 7 warps; grid 148 = #SMs

// scratch for gi = x @ W_ih^T + b_ih, per-b (k-independent)
__device__ float g_gi[BS * GI_COLS];   // [2048][768], 6 MB

// ---------------------------------------------------------------------------
// Kernel 1: gi[b][t*96+g] = sum_k x[b][k]*W_ih[t][g][k] + b_ih[t][g]
// C[2048,768] = A[2048,512] * B[768,512]^T + bias
// ---------------------------------------------------------------------------
__global__ void __launch_bounds__(256) gemm_gi_kernel(
    const float* __restrict__ A,
    const float* __restrict__ B,
    const float* __restrict__ bias)
{
    __shared__ float As[32][65];
    __shared__ float Bs[32][65];

    const int tid = threadIdx.x;
    const int tx  = tid & 15;
    const int ty  = tid >> 4;
    const int m0  = blockIdx.y * 64;
    const int n0  = blockIdx.x * 64;
    const int lr  = tid >> 3;
    const int lk  = (tid & 7) * 4;

    float acc[4][4];
#pragma unroll
    for (int i = 0; i < 4; i++)
#pragma unroll
        for (int j = 0; j < 4; j++) acc[i][j] = 0.f;

    for (int k0 = 0; k0 < NINP; k0 += 32) {
#pragma unroll
        for (int r = 0; r < 2; r++) {
            float4 va = *(const float4*)&A[(m0 + lr + r * 32) * NINP + k0 + lk];
            As[lk + 0][lr + r * 32] = va.x;
            As[lk + 1][lr + r * 32] = va.y;
            As[lk + 2][lr + r * 32] = va.z;
            As[lk + 3][lr + r * 32] = va.w;
            float4 vb = *(const float4*)&B[(n0 + lr + r * 32) * NINP + k0 + lk];
            Bs[lk + 0][lr + r * 32] = vb.x;
            Bs[lk + 1][lr + r * 32] = vb.y;
            Bs[lk + 2][lr + r * 32] = vb.z;
            Bs[lk + 3][lr + r * 32] = vb.w;
        }
        __syncthreads();
#pragma unroll
        for (int k = 0; k < 32; k++) {
            float a[4], b[4];
#pragma unroll
            for (int i = 0; i < 4; i++) a[i] = As[k][ty + i * 16];
#pragma unroll
            for (int j = 0; j < 4; j++) b[j] = Bs[k][tx + j * 16];
#pragma unroll
            for (int i = 0; i < 4; i++)
#pragma unroll
                for (int j = 0; j < 4; j++)
                    acc[i][j] = fmaf(a[i], b[j], acc[i][j]);
        }
        __syncthreads();
    }

#pragma unroll
    for (int j = 0; j < 4; j++) {
        float bj = bias[n0 + tx + j * 16];
#pragma unroll
        for (int i = 0; i < 4; i++)
            g_gi[(m0 + ty + i * 16) * GI_COLS + n0 + tx + j * 16] = acc[i][j] + bj;
    }
}

// ---------------------------------------------------------------------------
// Kernel 2: thread-per-n fused GRU + attention + hard gumbel select.
// All weight reads are warp-uniform LDS.128 broadcasts; zero shuffles.
// ---------------------------------------------------------------------------
#define SMEM_FLOATS (TT*96*MM + TT*MM*16 + MM*16 + TT*96)   // 29952
#define SMEM_BYTES  (SMEM_FLOATS * 4)                        // 119808

__global__ void __launch_bounds__(TPB, 1) fused2_kernel(
    const float* __restrict__ h,
    const float* __restrict__ W_hh,
    const float* __restrict__ b_hh,
    const float* __restrict__ w_read,
    const float* __restrict__ w_write,
    const float* __restrict__ gum,
    float* __restrict__ out)
{
    extern __shared__ float sm[];
    float* Wg  = sm;               // W_hh natural layout [t][g][m]: 24576
    float* Wwr = Wg + TT*96*MM;    // w_write [t][l][f]:             4096
    float* Wrd = Wwr + TT*MM*16;   // w_read [m][f]:                  512
    float* bh  = Wrd + MM*16;      // b_hh [t][g]:                    768
    const int tid = threadIdx.x;

    {   // stage weights (contiguous copies, float4)
        float4* d = (float4*)Wg; const float4* s = (const float4*)W_hh;
        for (int i = tid; i < TT*96*MM/4; i += TPB) d[i] = s[i];
        d = (float4*)Wwr; s = (const float4*)w_write;
        for (int i = tid; i < TT*MM*16/4; i += TPB) d[i] = s[i];
        d = (float4*)Wrd; s = (const float4*)w_read;
        for (int i = tid; i < MM*16/4; i += TPB) d[i] = s[i];
        d = (float4*)bh; s = (const float4*)b_hh;
        for (int i = tid; i < TT*96/4; i += TPB) d[i] = s[i];
    }
    __syncthreads();

    const int n = blockIdx.x * TPB + tid;
    if (n >= NTOT) return;          // no further block-wide syncs
    const int b = n >> 4;

    float h2[32];
    {
        const float4* hp = (const float4*)(h + n * MM);
#pragma unroll
        for (int i = 0; i < 8; i++) {
            float4 v = hp[i];
            h2[4*i] = v.x; h2[4*i+1] = v.y; h2[4*i+2] = v.z; h2[4*i+3] = v.w;
        }
    }

    // h_read[f] = sum_m h2[m] * w_read[m][f]
    float hr[16];
#pragma unroll
    for (int f = 0; f < 16; f++) hr[f] = 0.f;
#pragma unroll
    for (int m = 0; m < 32; m++) {
        const float4* w = (const float4*)(Wrd + m * 16);
        float hm = h2[m];
#pragma unroll
        for (int f4 = 0; f4 < 4; f4++) {
            float4 v = w[f4];
            hr[4*f4]   = fmaf(hm, v.x, hr[4*f4]);
            hr[4*f4+1] = fmaf(hm, v.y, hr[4*f4+1]);
            hr[4*f4+2] = fmaf(hm, v.z, hr[4*f4+2]);
            hr[4*f4+3] = fmaf(hm, v.w, hr[4*f4+3]);
        }
    }

    float rmax = -1e30f, rsum = 0.f;
    int amax = 0;
    float hall[TT][32];             // per-thread local (1 KB), STL/LDL

#pragma unroll 1
    for (int t = 0; t < TT; t++) {
        const float* gib = g_gi + b * GI_COLS + t * 96;
        const float* wt  = Wg  + t * 96 * MM;
        const float* wwt = Wwr + t * MM * 16;
        const float* bht = bh  + t * 96;
        float wk[16];
#pragma unroll
        for (int f = 0; f < 16; f++) wk[f] = 0.f;

#pragma unroll
        for (int l4 = 0; l4 < 8; l4++) {
            float Ga[4], Gb[4], Gc[4];
            *(float4*)Ga = *(const float4*)(gib + 4*l4);
            *(float4*)Gb = *(const float4*)(gib + 32 + 4*l4);
            *(float4*)Gc = *(const float4*)(gib + 64 + 4*l4);
#pragma unroll
            for (int li = 0; li < 4; li++) {
                const int l = 4*l4 + li;
                float ar = bht[l], az = bht[32 + l], an = bht[64 + l];
                const float4* wr = (const float4*)(wt + l * 32);
                const float4* wz = (const float4*)(wt + (32 + l) * 32);
                const float4* wn = (const float4*)(wt + (64 + l) * 32);
#pragma unroll
                for (int m4 = 0; m4 < 8; m4++) {
                    float4 a = wr[m4], bb = wz[m4], c = wn[m4];
                    ar = fmaf(a.x,  h2[4*m4],   ar);
                    ar = fmaf(a.y,  h2[4*m4+1], ar);
                    ar = fmaf(a.z,  h2[4*m4+2], ar);
                    ar = fmaf(a.w,  h2[4*m4+3], ar);
                    az = fmaf(bb.x, h2[4*m4],   az);
                    az = fmaf(bb.y, h2[4*m4+1], az);
                    az = fmaf(bb.z, h2[4*m4+2], az);
                    az = fmaf(bb.w, h2[4*m4+3], az);
                    an = fmaf(c.x,  h2[4*m4],   an);
                    an = fmaf(c.y,  h2[4*m4+1], an);
                    an = fmaf(c.z,  h2[4*m4+2], an);
                    an = fmaf(c.w,  h2[4*m4+3], an);
                }
                float r  = __fdividef(1.f, 1.f + __expf(-(Ga[li] + ar)));
                float z  = __fdividef(1.f, 1.f + __expf(-(Gb[li] + az)));
                float xn = Gc[li] + r * an;
                float e2 = __expf(-2.f * xn);
                float nn = __fdividef(1.f - e2, 1.f + e2);   // tanh
                float hn = (1.f - z) * nn + z * h2[l];
                hall[t][l] = hn;
                const float4* ww = (const float4*)(wwt + l * 16);
#pragma unroll
                for (int f4 = 0; f4 < 4; f4++) {
                    float4 v = ww[f4];
                    wk[4*f4]   = fmaf(hn, v.x, wk[4*f4]);
                    wk[4*f4+1] = fmaf(hn, v.y, wk[4*f4+1]);
                    wk[4*f4+2] = fmaf(hn, v.z, wk[4*f4+2]);
                    wk[4*f4+3] = fmaf(hn, v.w, wk[4*f4+3]);
                }
            }
        }
        float lg = 0.f;
#pragma unroll
        for (int f = 0; f < 16; f++) lg = fmaf(hr[f], wk[f], lg);
        float s = (lg + gum[n * TT + t]) * 2.0f;       // /TAU, TAU=0.5
        if (s > rmax) {
            rsum = rsum * __expf(rmax - s) + 1.f;
            rmax = s; amax = t;
        } else {
            rsum += __expf(s - rmax);
        }
    }

    float p = __fdividef(1.f, rsum);        // softmax value at argmax
    float attv = (1.f + p) - p;             // straight-through residual, exact

    float4* ho = (float4*)(out + n * MM);
#pragma unroll
    for (int l4 = 0; l4 < 8; l4++) {
        float4 v;
        v.x = attv * hall[amax][4*l4];
        v.y = attv * hall[amax][4*l4+1];
        v.z = attv * hall[amax][4*l4+2];
        v.w = attv * hall[amax][4*l4+3];
        ho[l4] = v;
    }
    float* ao = out + BS * NHID + n * TT;
#pragma unroll
    for (int t = 0; t < TT; t++) ao[t] = (t == amax) ? attv : 0.f;
}

// ---------------------------------------------------------------------------
extern "C" void kernel_launch(void* const* d_in, const int* in_sizes, int n_in,
                              void* d_out, int out_size)
{
    const float* x       = (const float*)d_in[0];
    const float* h       = (const float*)d_in[1];
    const float* W_ih    = (const float*)d_in[2];
    const float* W_hh    = (const float*)d_in[3];
    const float* b_ih    = (const float*)d_in[4];
    const float* b_hh    = (const float*)d_in[5];
    const float* w_read  = (const float*)d_in[6];
    const float* w_write = (const float*)d_in[7];
    const float* gum     = (const float*)d_in[8];
    float* out = (float*)d_out;

    dim3 g1(GI_COLS / 64, BS / 64);           // (12, 32)
    gemm_gi_kernel<<<g1, 256>>>(x, W_ih, b_ih);

    cudaFuncSetAttribute(fused2_kernel,
                         cudaFuncAttributeMaxDynamicSharedMemorySize, SMEM_BYTES);
    fused2_kernel<<<(NTOT + TPB - 1) / TPB, TPB, SMEM_BYTES>>>(
        h, W_hh, b_hh, w_read, w_write, gum, out);
}